// round 16
// baseline (speedup 1.0000x reference)
#include <cuda_runtime.h>
#include <cuda_fp16.h>
#include <math.h>
#include <stdint.h>

// ---------------- problem constants ----------------
#define Bq 4
#define Sq 512
#define Hq 1024
#define Iq 4096
#define Eq 8
#define Vq 32000
#define Lq 2
#define NHq 8
#define DHq 128
#define Tq (Bq*Sq)          // 2048 tokens

typedef long long ll;

__device__ __forceinline__ uint32_t smem_u32(const void* p) {
    uint32_t a;
    asm("{ .reg .u64 t; cvta.to.shared.u64 t, %1; cvt.u32.u64 %0, t; }" : "=r"(a) : "l"(p));
    return a;
}

// ---------------- device scratch (static, no allocs) ----------------
__device__ float g_x[Tq*Hq];
__device__ float g_n[Tq*Hq];
__device__ float g_moe[2*Tq*Hq];
__device__ int   g_sel[Tq*2];
__device__ int   g_cnt[Eq];
__device__ int   g_off[Eq];
__device__ int   g_cur[Eq];
__device__ int   g_tokmap[2*Tq];
__device__ int   g_outmap[2*Tq];
__device__ float g_aux[1];
__device__ float g_zb[512];      // zero bias (scores N-tile needs up to 512)
// fp16 planes
__device__ __half g_winH[Lq*3*Hq*Hq];
__device__ __half g_woutH[Lq*Hq*Hq];
__device__ __half g_f1H[(size_t)Lq*Eq*Iq*Hq];
__device__ __half g_f2H[(size_t)Lq*Eq*Hq*Iq];
__device__ __half g_lmH[(size_t)Vq*Hq];
__device__ __half g_nH[Tq*Hq];
__device__ __half g_qkvH[Tq*3*Hq];
__device__ __half g_vTH[Tq*Hq];
__device__ __half g_scH[(size_t)Bq*NHq*Sq*Sq];
__device__ __half g_pH[(size_t)Bq*NHq*Sq*Sq];
__device__ __half g_aoH[Tq*Hq];
__device__ __half g_xH[Tq*Hq];
__device__ __half g_hH[(size_t)2*Tq*Iq];

// ---------------- conversions ----------------
__global__ void cvt1_k(const float* __restrict__ src, __half* __restrict__ hi, ll total) {
    ll i = ((ll)blockIdx.x * 256 + threadIdx.x) * 8;
    if (i >= total) return;
    float4 a = *(const float4*)(src + i);
    float4 b = *(const float4*)(src + i + 4);
    float v[8] = {a.x, a.y, a.z, a.w, b.x, b.y, b.z, b.w};
    __align__(16) __half h[8];
    #pragma unroll
    for (int j = 0; j < 8; j++) h[j] = __float2half(v[j]);
    *(uint4*)(hi + i) = *(const uint4*)h;
}

// ---------------- HMMA fp16 split GEMM ----------------
// TERMS=3: C = Ah*Bh + Al*Bh + Ah*Bl   TERMS=2: C = (Ah+Al)*Bh   TERMS=1: C = Ah*Bh
// CTA tile 128xTN, K-slice BKT (32/64), 4-stage cp.async pipeline, 8 warps (2x4).
// EPI: 0=alpha(f32), 1=bias(f32), 2=bias+res(f32), 3=bias+gelu->hi/lo planes,
//      4=bias->hi/lo planes, 5=bias+gelu->hi only, 6=bias->hi only.
// MOE: 0 dense/batched, 1 gather-A/compact-C, 2 compact-A/scatter-C.
#define DS_T1_256_32 122880  // 4 stages x 30720  (TERMS=1, TN=256, BK=32)
#define DS_T1_128_32 81920   // 4 stages x 20480  (TERMS=1, TN=128, BK=32)
#define DS_T1_256_64 221184  // 4 stages x 55296  (TERMS=1, TN=256, BK=64)
#define DS_T1_128_64 147456  // 4 stages x 36864  (TERMS=1, TN=128, BK=64)

__device__ __forceinline__ void ldmx4(uint32_t* r, uint32_t addr) {
    asm volatile("ldmatrix.sync.aligned.m8n8.x4.shared.b16 {%0,%1,%2,%3}, [%4];"
        : "=r"(r[0]), "=r"(r[1]), "=r"(r[2]), "=r"(r[3]) : "r"(addr));
}
__device__ __forceinline__ void mma16816(float* c, const uint32_t* a, uint32_t b0, uint32_t b1) {
    asm volatile("mma.sync.aligned.m16n8k16.row.col.f32.f16.f16.f32 "
        "{%0,%1,%2,%3}, {%4,%5,%6,%7}, {%8,%9}, {%0,%1,%2,%3};"
        : "+f"(c[0]), "+f"(c[1]), "+f"(c[2]), "+f"(c[3])
        : "r"(a[0]), "r"(a[1]), "r"(a[2]), "r"(a[3]), "r"(b0), "r"(b1));
}
__device__ __forceinline__ void cpasync16(uint32_t dst, const void* src) {
    asm volatile("cp.async.cg.shared.global [%0], [%1], 16;" :: "r"(dst), "l"(src));
}
__device__ __forceinline__ void cpasync16z(uint32_t dst, const void* src, uint32_t sz) {
    asm volatile("cp.async.cg.shared.global [%0], [%1], 16, %2;" :: "r"(dst), "l"(src), "r"(sz));
}

template<int EPI, int MOE, int TN, int TERMS, int BKT>
__global__ __launch_bounds__(256, 1)
void bgemm(int M, int N, int K,
           const __half* __restrict__ Ah, const __half* __restrict__ Al, int lda,
           const __half* __restrict__ Bh, const __half* __restrict__ Bl, int ldb,
           void* __restrict__ Cv, __half* __restrict__ Clo, int ldc,
           const float* __restrict__ bias,
           const float* __restrict__ res,
           float alpha, int zdiv,
           ll sA1, ll sA2, ll sB1, ll sB2, ll sC1, ll sC2,
           ll sBz, ll sBiasZ)
{
    constexpr int WN     = TN / 4;
    constexpr int NF     = WN / 8;
    constexpr int NB16   = WN / 16;
    constexpr int APL    = (TERMS >= 2) ? 2 : 1;
    constexpr int BPL    = (TERMS == 3) ? 2 : 1;
    constexpr int STAGES = 4;
    constexpr int RSH    = BKT + 8;                // row stride in halves
    constexpr uint32_t APB = 128u * RSH * 2u;
    constexpr uint32_t BPB = (uint32_t)TN * RSH * 2u;
    constexpr uint32_t STB = APB * APL + BPB * BPL;
    constexpr uint32_t ALOFF = APB;
    constexpr uint32_t BHOFF = APB * APL;
    constexpr uint32_t BLOFF = BHOFF + BPB;

    int Me = M, rowbase = 0;
    ll coff = 0;
    if (MOE) {
        int z = blockIdx.z;
        Me = g_cnt[z]; rowbase = g_off[z];
        Bh += (ll)z * sBz; if (TERMS == 3) Bl += (ll)z * sBz;
        bias += (ll)z * sBiasZ;
    } else {
        int z = blockIdx.z;
        int zb = z / zdiv, zh = z - zb * zdiv;
        Ah += zb*sA1 + zh*sA2; if (TERMS >= 2) Al += zb*sA1 + zh*sA2;
        Bh += zb*sB1 + zh*sB2; if (TERMS == 3) Bl += zb*sB1 + zh*sB2;
        coff = zb*sC1 + zh*sC2;
    }
    int m0 = blockIdx.x * 128;
    if (m0 >= Me) return;
    int n0 = blockIdx.y * TN;

    __shared__ int s_row[128];
    __shared__ int s_cout[128];
    extern __shared__ __align__(16) char dsm[];
    uint32_t dbase = smem_u32(dsm);

    int tid = threadIdx.x, lane = tid & 31, wid = tid >> 5;
    int wm = wid >> 2, wn = wid & 3;

    if (tid < 128) {
        int grow = m0 + tid;
        int rid = -1, cid = -1;
        if (grow < Me) {
            if      (MOE == 1) { rid = g_tokmap[rowbase + grow]; cid = rowbase + grow; }
            else if (MOE == 2) { rid = rowbase + grow;           cid = g_outmap[rowbase + grow]; }
            else               { rid = grow;                     cid = grow; }
        }
        s_row[tid] = rid; s_cout[tid] = cid;
    }
    __syncthreads();

    float acc[4][NF][4];
    #pragma unroll
    for (int a = 0; a < 4; a++)
        #pragma unroll
        for (int b = 0; b < NF; b++)
            #pragma unroll
            for (int c = 0; c < 4; c++) acc[a][b][c] = 0.f;

    int S = K / BKT;

    auto load_stage = [&](int s) {
        int c0 = s * BKT;
        uint32_t base = dbase + (uint32_t)(s % STAGES) * STB;
        constexpr int CPR  = BKT / 8;
        constexpr int CH_A = 128 * CPR;
        constexpr int CH_B = TN * CPR;
        constexpr int ITER = (APL*CH_A + BPL*CH_B) / 256;
        #pragma unroll
        for (int j = 0; j < ITER; j++) {
            int idx = tid + j * 256;
            if (idx < CH_A) {
                int row = idx / CPR, c = idx % CPR;
                int r = s_row[row];
                ll aoff = (r >= 0) ? ((ll)r * lda + c0 + c * 8) : 0;
                cpasync16z(base + (uint32_t)(row*(RSH*2) + c*16), Ah + aoff, (r>=0)?16u:0u);
            } else if (APL == 2 && idx < 2*CH_A) {
                int k2 = idx - CH_A;
                int row = k2 / CPR, c = k2 % CPR;
                int r = s_row[row];
                ll aoff = (r >= 0) ? ((ll)r * lda + c0 + c * 8) : 0;
                cpasync16z(base + ALOFF + (uint32_t)(row*(RSH*2) + c*16), Al + aoff, (r>=0)?16u:0u);
            } else if (idx < APL*CH_A + CH_B) {
                int k2 = idx - APL*CH_A;
                int row = k2 / CPR, c = k2 % CPR;
                cpasync16(base + BHOFF + (uint32_t)(row*(RSH*2) + c*16),
                          Bh + (ll)(n0 + row) * ldb + c0 + c * 8);
            } else if (BPL == 2) {
                int k2 = idx - APL*CH_A - CH_B;
                int row = k2 / CPR, c = k2 % CPR;
                cpasync16(base + BLOFF + (uint32_t)(row*(RSH*2) + c*16),
                          Bl + (ll)(n0 + row) * ldb + c0 + c * 8);
            }
        }
        asm volatile("cp.async.commit_group;" ::: "memory");
    };

    #pragma unroll
    for (int i = 0; i < STAGES - 1; i++) load_stage(i);

    for (int s = 0; s < S; s++) {
        if (S - s - 1 >= STAGES - 2) {
            asm volatile("cp.async.wait_group %0;" :: "n"(STAGES - 2) : "memory");
        } else {
            asm volatile("cp.async.wait_group 0;" ::: "memory");
        }
        __syncthreads();
        if (s + STAGES - 1 < S) load_stage(s + STAGES - 1);

        uint32_t base = dbase + (uint32_t)(s % STAGES) * STB;
        uint32_t Ahb = base, Alb = base + ALOFF, Bhb = base + BHOFF, Blb = base + BLOFF;

        #pragma unroll
        for (int kk = 0; kk < BKT/16; kk++) {
            uint32_t ah[4][4], al[4][4];
            #pragma unroll
            for (int mf = 0; mf < 4; mf++) {
                uint32_t roff = (uint32_t)(((wm*64 + mf*16 + (lane & 15)) * RSH
                                            + kk*16 + (lane >> 4) * 8) * 2);
                ldmx4(ah[mf], Ahb + roff);
                if (TERMS >= 2) ldmx4(al[mf], Alb + roff);
            }
            int g = lane >> 3;
            #pragma unroll
            for (int bt = 0; bt < NB16; bt++) {
                uint32_t bhf[4], blf[4];
                uint32_t roff = (uint32_t)(((wn*WN + bt*16 + (g >> 1)*8 + (lane & 7)) * RSH
                                            + kk*16 + (g & 1) * 8) * 2);
                ldmx4(bhf, Bhb + roff);
                if (TERMS == 3) ldmx4(blf, Blb + roff);
                #pragma unroll
                for (int sub = 0; sub < 2; sub++) {
                    int nf = bt*2 + sub;
                    #pragma unroll
                    for (int mf = 0; mf < 4; mf++) {
                        mma16816(acc[mf][nf], ah[mf], bhf[sub*2], bhf[sub*2+1]);
                        if (TERMS >= 2)
                            mma16816(acc[mf][nf], al[mf], bhf[sub*2], bhf[sub*2+1]);
                        if (TERMS == 3)
                            mma16816(acc[mf][nf], ah[mf], blf[sub*2], blf[sub*2+1]);
                    }
                }
            }
        }
    }

    // ---------------- epilogue ----------------
    #pragma unroll
    for (int mf = 0; mf < 4; mf++) {
        int rbase = wm*64 + mf*16 + (lane >> 2);
        #pragma unroll
        for (int half = 0; half < 2; half++) {
            int rloc = rbase + half * 8;
            int cr = s_cout[rloc];
            if (cr < 0) continue;
            #pragma unroll
            for (int nf = 0; nf < NF; nf++) {
                int col = n0 + wn*WN + nf*8 + (lane & 3)*2;
                float v0 = acc[mf][nf][half*2 + 0] * alpha;
                float v1 = acc[mf][nf][half*2 + 1] * alpha;
                if (EPI >= 1) {
                    float2 bv = *(const float2*)&bias[col];
                    v0 += bv.x; v1 += bv.y;
                }
                if (EPI == 2) {
                    float2 rv = *(const float2*)(res + (ll)cr*ldc + col);
                    v0 += rv.x; v1 += rv.y;
                }
                if (EPI >= 3) {
                    if (EPI == 3 || EPI == 5) {
                        v0 = 0.5f*v0*(1.f + erff(v0*0.70710678118654752f));
                        v1 = 0.5f*v1*(1.f + erff(v1*0.70710678118654752f));
                    }
                    __half h0 = __float2half(v0);
                    __half h1 = __float2half(v1);
                    __half* DH = (__half*)Cv + coff + (ll)cr * ldc + col;
                    *(__half2*)DH = __halves2half2(h0, h1);
                    if (EPI == 3 || EPI == 4) {
                        __half l0 = __float2half(v0 - __half2float(h0));
                        __half l1 = __float2half(v1 - __half2float(h1));
                        __half* DL = Clo + coff + (ll)cr * ldc + col;
                        *(__half2*)DL = __halves2half2(l0, l1);
                    }
                } else {
                    *(float2*)((float*)Cv + coff + (ll)cr*ldc + col) = make_float2(v0, v1);
                }
            }
        }
    }
}

// ---------------- V transpose: qkv hi plane -> per-(b,h) V^T hi plane ----------------
__global__ void vtrans_k(const __half* __restrict__ qH, __half* __restrict__ vTH) {
    int z = blockIdx.z; int b = z >> 3; int h = z & 7;
    int d0 = blockIdx.y * 32;
    int s0 = blockIdx.x * 32;
    __shared__ __half tH[32][33];
    int tx = threadIdx.x, ty = threadIdx.y;   // 32 x 8
    #pragma unroll
    for (int i = 0; i < 4; i++) {
        int sl = ty*4 + i;
        ll src = (ll)(b*Sq + s0 + sl)*(3*Hq) + 2*Hq + h*DHq + d0 + tx;
        tH[sl][tx] = qH[src];
    }
    __syncthreads();
    #pragma unroll
    for (int i = 0; i < 4; i++) {
        int dl = ty*4 + i;
        ll dst = ((ll)z*DHq + d0 + dl)*Sq + s0 + tx;
        vTH[dst] = tH[tx][dl];
    }
}

// ---------------- small kernels ----------------
// embed + init aux/zero-bias (block 0)
__global__ void embed_k(const int* __restrict__ ids, const float* __restrict__ emb) {
    if (blockIdx.x == 0) {
        if (threadIdx.x == 0) g_aux[0] = 0.f;
        for (int i = threadIdx.x; i < 512; i += 256) g_zb[i] = 0.f;
    }
    int idx = blockIdx.x*256 + threadIdx.x;
    int t = idx / Hq, h = idx - t*Hq;
    g_x[idx] = emb[(ll)ids[t]*Hq + h];
}

// LayerNorm: emits fp16 hi plane always; fp32 output + cnt-zeroing optional
__global__ void ln_k(const float* __restrict__ x, const float* __restrict__ g,
                     const float* __restrict__ b, float* __restrict__ o,
                     __half* __restrict__ oH, int flags) {
    int t = blockIdx.x;
    if ((flags & 2) && t == 0 && threadIdx.x < Eq) g_cnt[threadIdx.x] = 0;
    const float* xr = x + (ll)t*Hq;
    int tid = threadIdx.x;
    float v[4]; float s = 0.f;
    #pragma unroll
    for (int i = 0; i < 4; i++) { v[i] = xr[tid + 256*i]; s += v[i]; }
    __shared__ float red[256];
    red[tid] = s; __syncthreads();
    for (int o2 = 128; o2; o2 >>= 1) { if (tid < o2) red[tid] += red[tid+o2]; __syncthreads(); }
    float mu = red[0] * (1.f/Hq);
    __syncthreads();
    s = 0.f;
    #pragma unroll
    for (int i = 0; i < 4; i++) { float d = v[i]-mu; s += d*d; }
    red[tid] = s; __syncthreads();
    for (int o2 = 128; o2; o2 >>= 1) { if (tid < o2) red[tid] += red[tid+o2]; __syncthreads(); }
    float inv = rsqrtf(red[0]*(1.f/Hq) + 1e-5f);
    float* orow = o + (ll)t*Hq;
    __half* hr = oH + (ll)t*Hq;
    #pragma unroll
    for (int i = 0; i < 4; i++) {
        int h = tid + 256*i;
        float y = (v[i]-mu)*inv*g[h] + b[h];
        if (flags & 1) orow[h] = y;
        hr[h] = __float2half(y);
    }
}

__global__ void softmax_k(const __half* __restrict__ sc, __half* __restrict__ pH) {
    ll row = blockIdx.x;
    const __half* r = sc + row*Sq;
    int tid = threadIdx.x;
    float a = __half2float(r[tid]), b = __half2float(r[tid+256]);
    __shared__ float red[256];
    red[tid] = fmaxf(a,b); __syncthreads();
    for (int o = 128; o; o >>= 1) { if (tid < o) red[tid] = fmaxf(red[tid], red[tid+o]); __syncthreads(); }
    float m = red[0]; __syncthreads();
    a = expf(a-m); b = expf(b-m);
    red[tid] = a+b; __syncthreads();
    for (int o = 128; o; o >>= 1) { if (tid < o) red[tid] += red[tid+o]; __syncthreads(); }
    float inv = 1.f/red[0];
    pH[row*Sq + tid]       = __float2half(a*inv);
    pH[row*Sq + tid + 256] = __float2half(b*inv);
}

__global__ void router_k(const float* __restrict__ n2, const float* __restrict__ rw,
                         const float* __restrict__ rb) {
    int t = blockIdx.x;
    int w = threadIdx.x >> 5, lane = threadIdx.x & 31;
    const float* xr = n2 + (ll)t*Hq;
    const float* wr = rw + (ll)w*Hq;
    float s = 0.f;
    for (int h = lane; h < Hq; h += 32) s += xr[h]*wr[h];
    #pragma unroll
    for (int o = 16; o; o >>= 1) s += __shfl_xor_sync(0xffffffffu, s, o);
    __shared__ float lg[Eq];
    if (lane == 0) lg[w] = s + rb[w];
    __syncthreads();
    if (threadIdx.x == 0) {
        int b0 = 0; float v0 = lg[0];
        for (int e = 1; e < Eq; e++) if (lg[e] > v0) { v0 = lg[e]; b0 = e; }
        int b1 = -1; float v1 = -3.4e38f;
        for (int e = 0; e < Eq; e++) { if (e == b0) continue; if (lg[e] > v1) { v1 = lg[e]; b1 = e; } }
        g_sel[2*t]   = b0;
        g_sel[2*t+1] = b1;
        atomicAdd(&g_cnt[b0], 1);
        atomicAdd(&g_cnt[b1], 1);
    }
}

// offsets + aux loss fused (1 thread)
__global__ void offsets_k() {
    int s = 0;
    float acc = 0.f;
    const float target = (float)Tq / (float)Eq;
    for (int e = 0; e < Eq; e++) {
        g_off[e] = s; g_cur[e] = s; s += g_cnt[e];
        float d = (float)g_cnt[e] - target;
        acc += d*d;
    }
    g_aux[0] += 0.01f * acc / (float)Eq;
}

__global__ void build_k() {
    int t = blockIdx.x*256 + threadIdx.x;
    if (t >= Tq) return;
    #pragma unroll
    for (int slot = 0; slot < 2; slot++) {
        int e = g_sel[2*t + slot];
        int p = atomicAdd(&g_cur[e], 1);
        g_tokmap[p] = t;
        g_outmap[p] = slot*Tq + t;
    }
}

// combine + optional hi plane emission (lm-head input after last layer)
__global__ void combine_k(__half* __restrict__ xH) {
    int idx = blockIdx.x*256 + threadIdx.x;
    float v = g_x[idx] + g_moe[idx] + g_moe[(ll)Tq*Hq + idx];
    g_x[idx] = v;
    if (xH) xH[idx] = __float2half(v);
}

__global__ void tail_k(float* __restrict__ out, ll out_size) {
    ll base = (ll)Tq * Vq;
    for (ll i = base + threadIdx.x; i < out_size; i += 256)
        out[i] = g_aux[0];
}

// ---------------- launch ----------------
static inline int cv8blocks(ll total) { return (int)((total/8 + 255) / 256); }

extern "C" void kernel_launch(void* const* d_in, const int* in_sizes, int n_in,
                              void* d_out, int out_size) {
    const int*   ids  = (const int*)  d_in[0];
    const float* emb  = (const float*)d_in[1];
    const float* ln1g = (const float*)d_in[2];
    const float* ln1b = (const float*)d_in[3];
    const float* aiw  = (const float*)d_in[4];
    const float* aib  = (const float*)d_in[5];
    const float* aow  = (const float*)d_in[6];
    const float* aob  = (const float*)d_in[7];
    const float* ln2g = (const float*)d_in[8];
    const float* ln2b = (const float*)d_in[9];
    const float* rw   = (const float*)d_in[10];
    const float* rb   = (const float*)d_in[11];
    const float* f1w  = (const float*)d_in[12];
    const float* f1b  = (const float*)d_in[13];
    const float* f2w  = (const float*)d_in[14];
    const float* f2b  = (const float*)d_in[15];
    const float* lmw  = (const float*)d_in[16];
    const float* lmb  = (const float*)d_in[17];
    float* out = (float*)d_out;

    cudaFuncSetAttribute(bgemm<6,0,256,1,64>, cudaFuncAttributeMaxDynamicSharedMemorySize, DS_T1_256_64);
    cudaFuncSetAttribute(bgemm<6,0,256,1,32>, cudaFuncAttributeMaxDynamicSharedMemorySize, DS_T1_256_32);
    cudaFuncSetAttribute(bgemm<6,0,128,1,32>, cudaFuncAttributeMaxDynamicSharedMemorySize, DS_T1_128_32);
    cudaFuncSetAttribute(bgemm<2,0,128,1,64>, cudaFuncAttributeMaxDynamicSharedMemorySize, DS_T1_128_64);
    cudaFuncSetAttribute(bgemm<5,1,256,1,64>, cudaFuncAttributeMaxDynamicSharedMemorySize, DS_T1_256_64);
    cudaFuncSetAttribute(bgemm<1,2,256,1,64>, cudaFuncAttributeMaxDynamicSharedMemorySize, DS_T1_256_64);
    cudaFuncSetAttribute(bgemm<1,0,256,1,64>, cudaFuncAttributeMaxDynamicSharedMemorySize, DS_T1_256_64);

    float *px, *pn, *pmoe;
    cudaGetSymbolAddress((void**)&px,   g_x);
    cudaGetSymbolAddress((void**)&pn,   g_n);
    cudaGetSymbolAddress((void**)&pmoe, g_moe);
    float* pzb; cudaGetSymbolAddress((void**)&pzb, g_zb);
    __half *winH,*woutH,*f1H,*f2H,*lmH;
    __half *nH,*qkvH,*vTH,*scH,*pH,*aoH,*xH,*hH;
    cudaGetSymbolAddress((void**)&winH,  g_winH);
    cudaGetSymbolAddress((void**)&woutH, g_woutH);
    cudaGetSymbolAddress((void**)&f1H,   g_f1H);
    cudaGetSymbolAddress((void**)&f2H,   g_f2H);
    cudaGetSymbolAddress((void**)&lmH,   g_lmH);
    cudaGetSymbolAddress((void**)&nH,    g_nH);
    cudaGetSymbolAddress((void**)&qkvH,  g_qkvH);
    cudaGetSymbolAddress((void**)&vTH,   g_vTH);
    cudaGetSymbolAddress((void**)&scH,   g_scH);
    cudaGetSymbolAddress((void**)&pH,    g_pH);
    cudaGetSymbolAddress((void**)&aoH,   g_aoH);
    cudaGetSymbolAddress((void**)&xH,    g_xH);
    cudaGetSymbolAddress((void**)&hH,    g_hH);

    // ---- weight conversions (hi-only) ----
    cvt1_k<<<cv8blocks((ll)Lq*3*Hq*Hq),  256>>>(aiw, winH,  (ll)Lq*3*Hq*Hq);
    cvt1_k<<<cv8blocks((ll)Lq*Hq*Hq),    256>>>(aow, woutH, (ll)Lq*Hq*Hq);
    cvt1_k<<<cv8blocks((ll)Lq*Eq*Iq*Hq), 256>>>(f1w, f1H, (ll)Lq*Eq*Iq*Hq);
    cvt1_k<<<cv8blocks((ll)Lq*Eq*Hq*Iq), 256>>>(f2w, f2H, (ll)Lq*Eq*Hq*Iq);
    cvt1_k<<<cv8blocks((ll)Vq*Hq),       256>>>(lmw, lmH, (ll)Vq*Hq);

    embed_k<<<(Tq*Hq)/256, 256>>>(ids, emb);

    for (int l = 0; l < Lq; l++) {
        // --- attention ---
        ln_k<<<Tq,256>>>(px, ln1g + (ll)l*Hq, ln1b + (ll)l*Hq, pn, nH, 0);

        // qkv = n1 @ W_in^T + b  (1-term, BK=64) -> hi plane only
        bgemm<6,0,256,1,64><<<dim3(Tq/128, 3*Hq/256, 1), 256, DS_T1_256_64>>>(
            Tq, 3*Hq, Hq, nH, nullptr, Hq,
            winH + (ll)l*3*Hq*Hq, nullptr, Hq,
            qkvH, nullptr, 3*Hq, aib + (ll)l*3*Hq, nullptr,
            1.f, 1, 0,0,0,0,0,0, 0,0);

        // V^T hi plane per (b,h)
        vtrans_k<<<dim3(Sq/32, DHq/32, Bq*NHq), dim3(32,8)>>>(qkvH, vTH);

        // scores = q @ k^T / sqrt(DH)  (1-term, batched) -> fp16 scores
        bgemm<6,0,256,1,32><<<dim3(Sq/128, Sq/256, Bq*NHq), 256, DS_T1_256_32>>>(
            Sq, Sq, DHq, qkvH, nullptr, 3*Hq,
            qkvH + Hq, nullptr, 3*Hq,
            scH, nullptr, Sq, pzb, nullptr,
            1.f/11.313708498984761f, NHq,
            (ll)Sq*3*Hq, DHq, (ll)Sq*3*Hq, DHq, (ll)NHq*Sq*Sq, (ll)Sq*Sq,
            0, 0);

        softmax_k<<<Bq*NHq*Sq, 256>>>(scH, pH);

        // o = attn @ v  (1-term, batched) -> ao hi plane only
        bgemm<6,0,128,1,32><<<dim3(Sq/128, DHq/128, Bq*NHq), 256, DS_T1_128_32>>>(
            Sq, DHq, Sq, pH, nullptr, Sq,
            vTH, nullptr, Sq,
            aoH, nullptr, Hq, pzb, nullptr,
            1.f, NHq,
            (ll)NHq*Sq*Sq, (ll)Sq*Sq, (ll)NHq*DHq*Sq, (ll)DHq*Sq,
            (ll)Sq*Hq, DHq,
            0, 0);

        // x = x + o @ W_out^T + b  (1-term, BK=64)
        bgemm<2,0,128,1,64><<<dim3(Tq/128, Hq/128, 1), 256, DS_T1_128_64>>>(
            Tq, Hq, Hq, aoH, nullptr, Hq,
            woutH + (ll)l*Hq*Hq, nullptr, Hq,
            px, nullptr, Hq, aob + (ll)l*Hq, px,
            1.f, 1, 0,0,0,0,0,0, 0,0);

        // --- MoE ---
        ln_k<<<Tq,256>>>(px, ln2g + (ll)l*Hq, ln2b + (ll)l*Hq, pn, nH, 3);

        router_k<<<Tq,256>>>(pn, rw + (ll)l*Eq*Hq, rb + (ll)l*Eq);
        offsets_k<<<1,1>>>();
        build_k<<<Tq/256,256>>>();

        // fc1: gather, gelu, write hi-plane hidden  (1-term, BK=64)
        bgemm<5,1,256,1,64><<<dim3(Tq/128, Iq/256, Eq), 256, DS_T1_256_64>>>(
            Tq, Iq, Hq, nH, nullptr, Hq,
            f1H + (ll)l*Eq*Iq*Hq, nullptr, Hq,
            hH, nullptr, Iq, f1b + (ll)l*Eq*Iq, nullptr,
            1.f, 1, 0,0,0,0,0,0, (ll)Iq*Hq, (ll)Iq);

        // fc2: scatter to per-slot fp32 buffers  (1-term, BK=64)
        bgemm<1,2,256,1,64><<<dim3(Tq/128, Hq/256, Eq), 256, DS_T1_256_64>>>(
            Tq, Hq, Iq, hH, nullptr, Iq,
            f2H + (ll)l*Eq*Hq*Iq, nullptr, Iq,
            pmoe, nullptr, Hq, f2b + (ll)l*Eq*Hq, nullptr,
            1.f, 1, 0,0,0,0,0,0, (ll)Hq*Iq, (ll)Hq);

        // combine; on last layer also emit x hi plane for lm head
        bool last = (l == Lq - 1);
        combine_k<<<(Tq*Hq)/256, 256>>>(last ? xH : nullptr);
    }

    // lm head  (1-term, BK=64)
    bgemm<1,0,256,1,64><<<dim3(Tq/128, Vq/256, 1), 256, DS_T1_256_64>>>(
        Tq, Vq, Hq, xH, nullptr, Hq, lmH, nullptr, Hq, out, nullptr, Vq,
        lmb, nullptr, 1.f, 1, 0,0,0,0,0,0, 0, 0);

    tail_k<<<1,256>>>(out, (ll)out_size);
}